// round 3
// baseline (speedup 1.0000x reference)
#include <cuda_runtime.h>
#include <math.h>

#define NT     365
#define NGRID  2048
#define NX     16
#define NH     256
#define G4     1024              // 4*NH
#define K2     512               // combined k = NH (h) + NH (x0)
#define NROWS  (NT * NGRID)      // 747520

typedef unsigned long long ull;

// ---------------- scratch (static __device__, no allocations) ----------------
// keep total static size well under 2 GB (GOTPCREL link limit)
__device__ float g_x0[(size_t)NROWS * NH];            // ~765 MB
__device__ float g_wc[(K2 + 4) * G4];                 // combined [k][u][gate], +4 pad rows

__device__ __forceinline__ float sigf(float x) {
    return 1.0f / (1.0f + __expf(-x));
}

// packed fp32x2 fma: d = a*b + d  (Blackwell dual-lane FFMA)
__device__ __forceinline__ void fma2(ull& d, ull a, ull b) {
    asm("fma.rn.f32x2 %0, %1, %2, %0;" : "+l"(d) : "l"(a), "l"(b));
}
__device__ __forceinline__ ull dup2(float x) {
    ull r;
    asm("mov.b64 %0, {%1, %1};" : "=l"(r) : "f"(x));
    return r;
}
__device__ __forceinline__ float2 unpk(ull v) {
    float2 r;
    asm("mov.b64 {%0, %1}, %2;" : "=f"(r.x), "=f"(r.y) : "l"(v));
    return r;
}

// ---------------- kernel 0: pack combined weights ----------------
// act vector: k in [0,256) -> h[k], k in [256,512) -> x0[k-256]
// g_wc[(k*NH+u)*4+g] = (k<256) ? w_hh[(g*256+u)*256+k] : w_ih[(g*256+u)*256+(k-256)]
// As ull pairs: index (k*NH+u)*2 + 0 -> (wi,wf),  +1 -> (wg,wo)
__global__ void pack_weights(const float* __restrict__ w_ih,
                             const float* __restrict__ w_hh) {
    int idx = blockIdx.x * blockDim.x + threadIdx.x;   // 0 .. 512*1024-1
    int k = idx >> 10;            // 0..511
    int j = idx & 1023;           // gate-major row
    int g = j >> 8;
    int u = j & 255;
    float v = (k < NH) ? w_hh[j * NH + k] : w_ih[j * NH + (k - NH)];
    g_wc[((size_t)k * NH + u) * 4 + g] = v;
}

// ---------------- kernel 1: x0 = relu(x @ w_in^T + b_in) ----------------
__global__ __launch_bounds__(256) void in_proj(const float* __restrict__ x,
                                               const float* __restrict__ w_in,
                                               const float* __restrict__ b_in) {
    __shared__ float ws[NX][NH];
    __shared__ float xs[16][NX];
    int tid = threadIdx.x;
    for (int i = tid; i < NH * NX; i += 256) {
        int u = i >> 4, k = i & 15;
        ws[k][u] = w_in[i];
    }
    size_t row0 = (size_t)blockIdx.x * 16;
    {
        int r = tid >> 4, k = tid & 15;
        xs[r][k] = x[(row0 + r) * NX + k];
    }
    __syncthreads();
    int u = tid;
    float b = b_in[u];
#pragma unroll 4
    for (int r = 0; r < 16; r++) {
        float s = b;
#pragma unroll
        for (int k = 0; k < NX; k++) s = fmaf(xs[r][k], ws[k][u], s);
        g_x0[(row0 + r) * NH + u] = fmaxf(s, 0.0f);
    }
}

// ---------------- kernel 2: persistent fused LSTM scan (f32x2) ----------------
// 128 CTAs x 256 threads, CTA owns 16 batch rows for all 365 steps.
// Activations stored DUPLICATED in smem: act2[m][k] = (a,a) as 8B word, so one
// broadcast LDS.64 feeds both lanes of fma.rn.f32x2. Gates paired (i,f) / (g,o):
// weight float4 (wi,wf,wg,wo) is exactly two f32x2 multiplicands.
__global__ __launch_bounds__(256, 1) void lstm_scan(const float* __restrict__ b_ih,
                                                    const float* __restrict__ b_hh,
                                                    const float* __restrict__ w_out,
                                                    const float* __restrict__ b_out,
                                                    float* __restrict__ out) {
    extern __shared__ ull act2[];            // [16][K2] = 64 KB
    __shared__ float wout_s[NH];

    const int tid = threadIdx.x;
    const int u = tid;
    const int lane = tid & 31;
    const int wid = tid >> 5;
    const size_t row0 = (size_t)blockIdx.x * 16;

    wout_s[u] = w_out[u];

    float bi = b_ih[0 * NH + u] + b_hh[0 * NH + u];
    float bf = b_ih[1 * NH + u] + b_hh[1 * NH + u];
    float bg = b_ih[2 * NH + u] + b_hh[2 * NH + u];
    float bo = b_ih[3 * NH + u] + b_hh[3 * NH + u];

#pragma unroll
    for (int m = 0; m < 16; m++) {
        act2[m * K2 + u] = 0ULL;                                  // h = (0,0)
        act2[m * K2 + NH + u] = dup2(g_x0[(row0 + m) * NH + u]);  // x0(t=0)
    }

    float c_reg[16];
#pragma unroll
    for (int m = 0; m < 16; m++) c_reg[m] = 0.0f;

    const float b_out0 = b_out[0];
    const ull* __restrict__ Wp = reinterpret_cast<const ull*>(g_wc);  // (k*NH+u)*2 + {0,1}
    __syncthreads();

    for (int t = 0; t < NT; t++) {
        ull acc_if[16], acc_go[16];
        const ull z = 0ULL;
#pragma unroll
        for (int m = 0; m < 16; m++) { acc_if[m] = z; acc_go[m] = z; }

        // [h ; x0] @ Wc^T, k in chunks of 4 with one-chunk-ahead weight prefetch
        ull wif[4], wgo[4];
#pragma unroll
        for (int j = 0; j < 4; j++) {
            wif[j] = Wp[((size_t)j * NH + u) * 2 + 0];
            wgo[j] = Wp[((size_t)j * NH + u) * 2 + 1];
        }
        for (int kc = 0; kc < K2; kc += 4) {
            ull nif[4], ngo[4];
#pragma unroll
            for (int j = 0; j < 4; j++) {   // pad rows keep this in-bounds at kc=508
                nif[j] = Wp[((size_t)(kc + 4 + j) * NH + u) * 2 + 0];
                ngo[j] = Wp[((size_t)(kc + 4 + j) * NH + u) * 2 + 1];
            }
#pragma unroll
            for (int m = 0; m < 16; m++) {
                const ull* ar = &act2[m * K2 + kc];
                ull a0 = ar[0], a1 = ar[1], a2 = ar[2], a3 = ar[3];
                fma2(acc_if[m], a0, wif[0]); fma2(acc_go[m], a0, wgo[0]);
                fma2(acc_if[m], a1, wif[1]); fma2(acc_go[m], a1, wgo[1]);
                fma2(acc_if[m], a2, wif[2]); fma2(acc_go[m], a2, wgo[2]);
                fma2(acc_if[m], a3, wif[3]); fma2(acc_go[m], a3, wgo[3]);
            }
#pragma unroll
            for (int j = 0; j < 4; j++) { wif[j] = nif[j]; wgo[j] = ngo[j]; }
        }
        __syncthreads();   // all reads of act2 (step t state) done

        // activations + state update; write h(t) dup, preload x0(t+1) dup
#pragma unroll
        for (int m = 0; m < 16; m++) {
            float2 vif = unpk(acc_if[m]);
            float2 vgo = unpk(acc_go[m]);
            float iv = sigf(vif.x + bi);
            float fv = sigf(vif.y + bf);
            float gv = tanhf(vgo.x + bg);
            float ov = sigf(vgo.y + bo);
            float c  = fmaf(fv, c_reg[m], iv * gv);
            c_reg[m] = c;
            act2[m * K2 + u] = dup2(ov * tanhf(c));
            if (t + 1 < NT)
                act2[m * K2 + NH + u] =
                    dup2(g_x0[((size_t)(t + 1) * NGRID + row0 + m) * NH + u]);
        }
        __syncthreads();   // act2 for step t+1 ready (h part = h(t))

        // output projection for step t (reads h part only; read-only vs next k-loop)
#pragma unroll
        for (int mm = 0; mm < 2; mm++) {
            int m = wid * 2 + mm;
            float s = 0.0f;
#pragma unroll
            for (int q = 0; q < 8; q++) {
                int uu = lane + q * 32;
                s = fmaf(unpk(act2[m * K2 + uu]).x, wout_s[uu], s);
            }
#pragma unroll
            for (int off = 16; off; off >>= 1) s += __shfl_down_sync(0xffffffffu, s, off);
            if (lane == 0) out[(size_t)t * NGRID + row0 + m] = s + b_out0;
        }
    }
}

// ---------------- launch ----------------
extern "C" void kernel_launch(void* const* d_in, const int* in_sizes, int n_in,
                              void* d_out, int out_size) {
    const float* x     = (const float*)d_in[0];
    const float* w_in  = (const float*)d_in[1];
    const float* b_in  = (const float*)d_in[2];
    const float* w_ih  = (const float*)d_in[3];
    const float* w_hh  = (const float*)d_in[4];
    const float* b_ih  = (const float*)d_in[5];
    const float* b_hh  = (const float*)d_in[6];
    const float* w_out = (const float*)d_in[7];
    const float* b_out = (const float*)d_in[8];
    float* out = (float*)d_out;

    const int smem_scan = 16 * K2 * (int)sizeof(ull);   // 64 KB dynamic
    cudaFuncSetAttribute(lstm_scan, cudaFuncAttributeMaxDynamicSharedMemorySize,
                         smem_scan);

    pack_weights<<<K2 * G4 / 256, 256>>>(w_ih, w_hh);
    in_proj<<<NROWS / 16, 256>>>(x, w_in, b_in);
    lstm_scan<<<NGRID / 16, 256, smem_scan>>>(b_ih, b_hh, w_out, b_out, out);
}

// round 5
// speedup vs baseline: 1.5021x; 1.5021x over previous
#include <cuda_runtime.h>
#include <math.h>

#define NT     365
#define NGRID  2048
#define NX     16
#define NH     256
#define G4     1024              // 4*NH
#define K2     512               // combined k = NH (h) + NH (x0)
#define NROWS  (NT * NGRID)      // 747520
#define KSUB   64                // K2/8
#define SROW   520               // padded act row stride (floats)

// ---------------- scratch (static __device__) -- keep total < 2GB ----------------
__device__ float  g_x0[(size_t)NROWS * NH];            // ~765 MB
__device__ float4 g_bp[8 * KSUB * 16 * 32];            // packed B fragments, 4 MB

__device__ __host__ __forceinline__ int kpos(int j) { return (j < 4) ? 2 * j : 2 * j - 7; }

__device__ __forceinline__ unsigned tf32r(float x) {
    unsigned r; asm("cvt.rna.tf32.f32 %0, %1;" : "=r"(r) : "f"(x)); return r;
}
__device__ __forceinline__ float sigf(float x) { return 1.0f / (1.0f + __expf(-x)); }

__device__ __forceinline__ void mma8(float& c0, float& c1, float& c2, float& c3,
                                     unsigned a0, unsigned a1, unsigned a2, unsigned a3,
                                     unsigned b0, unsigned b1) {
    asm("mma.sync.aligned.m16n8k8.row.col.f32.tf32.tf32.f32 "
        "{%0,%1,%2,%3},{%4,%5,%6,%7},{%8,%9},{%0,%1,%2,%3};"
        : "+f"(c0), "+f"(c1), "+f"(c2), "+f"(c3)
        : "r"(a0), "r"(a1), "r"(a2), "r"(a3), "r"(b0), "r"(b1));
}

// ---------------- kernel 0: pack B fragments (hi/lo tf32) ----------------
// B[k][col]: col=(u<<2)|gate; k<256 -> w_hh[gate*NH+u][k], else w_ih[...][k-256]
// frag elem for (w,ks,ns,lane): b0 = B[8ks+tig][128w+8ns+g], b1 = B[8ks+tig+4][same]
__global__ void pack_weights(const float* __restrict__ w_ih,
                             const float* __restrict__ w_hh) {
    int idx = blockIdx.x * 256 + threadIdx.x;        // 0..262143
    int lane = idx & 31, ns = (idx >> 5) & 15, ks = (idx >> 9) & 63, w = idx >> 15;
    int g = lane >> 2, tig = lane & 3;
    int col = w * 128 + ns * 8 + g;
    int u = col >> 2, gate = col & 3;
    int jrow = gate * NH + u;
    int k0 = ks * 8 + tig, k1 = k0 + 4;
    float v0 = (k0 < NH) ? w_hh[jrow * NH + k0] : w_ih[jrow * NH + k0 - NH];
    float v1 = (k1 < NH) ? w_hh[jrow * NH + k1] : w_ih[jrow * NH + k1 - NH];
    unsigned h0 = tf32r(v0), h1 = tf32r(v1);
    unsigned l0 = tf32r(v0 - __uint_as_float(h0));
    unsigned l1 = tf32r(v1 - __uint_as_float(h1));
    g_bp[idx] = make_float4(__uint_as_float(h0), __uint_as_float(h1),
                            __uint_as_float(l0), __uint_as_float(l1));
}

// ---------------- kernel 1: x0 = relu(x @ w_in^T + b_in) ----------------
__global__ __launch_bounds__(256) void in_proj(const float* __restrict__ x,
                                               const float* __restrict__ w_in,
                                               const float* __restrict__ b_in) {
    __shared__ float ws[NX][NH];
    __shared__ float xs[16][NX];
    int tid = threadIdx.x;
    for (int i = tid; i < NH * NX; i += 256) {
        int u = i >> 4, k = i & 15;
        ws[k][u] = w_in[i];
    }
    size_t row0 = (size_t)blockIdx.x * 16;
    {
        int r = tid >> 4, k = tid & 15;
        xs[r][k] = x[(row0 + r) * NX + k];
    }
    __syncthreads();
    int u = tid;
    float b = b_in[u];
#pragma unroll 4
    for (int r = 0; r < 16; r++) {
        float s = b;
#pragma unroll
        for (int k = 0; k < NX; k++) s = fmaf(xs[r][k], ws[k][u], s);
        g_x0[(row0 + r) * NH + u] = fmaxf(s, 0.0f);
    }
}

// ---------------- kernel 2: persistent fused LSTM scan, 3xTF32 mma ----------------
// 128 CTAs x 256 threads (8 warps). CTA owns 16 rows. Warp w owns gate-interleaved
// N-slice [128w,128w+128). A = [16 rows][512 k] act (h|x0), hi+lo tf32 in SMEM with
// per-8-group k-permutation so each fragment reg-pair is one LDS.64.
// PTX m16n8k8 A-frag map: a0=(g0,tig) a1=(g0+8,tig) a2=(g0,tig+4) a3=(g0+8,tig+4);
// our h01=(A[g0][tig],A[g0][tig+4]), h23=(A[g0+8][tig],A[g0+8][tig+4]) ->
// pass (h01.x, h23.x, h01.y, h23.y).   [R4 bug: a1/a2 were swapped]
__global__ __launch_bounds__(256, 1) void lstm_scan(const float* __restrict__ b_ih,
                                                    const float* __restrict__ b_hh,
                                                    const float* __restrict__ w_out,
                                                    const float* __restrict__ b_out,
                                                    float* __restrict__ out) {
    extern __shared__ unsigned smemu[];
    // layout (words): actH [16*SROW], actL [16*SROW], bias[1024], wout[256], outp[16*8]
    const int AH = 0, AL = 16 * SROW, BI = 2 * 16 * SROW, WO = BI + 1024, OP = WO + 256;
    float* biasf = (float*)&smemu[BI];
    float* woutf = (float*)&smemu[WO];
    float* outpf = (float*)&smemu[OP];

    const int tid = threadIdx.x;
    const int w = tid >> 5, lane = tid & 31;
    const int g0 = lane >> 2, tig = lane & 3;
    const size_t row0 = (size_t)blockIdx.x * 16;
    const float b_out0 = b_out[0];

    // init bias / wout / act
    for (int j = tid; j < G4; j += 256)
        biasf[j] = b_ih[(j & 3) * NH + (j >> 2)] + b_hh[(j & 3) * NH + (j >> 2)];
    woutf[tid] = w_out[tid];
    for (int i = tid; i < 16 * SROW; i += 256) { smemu[AH + i] = 0u; smemu[AL + i] = 0u; }
    __syncthreads();
    {   // x0(t=0): thread handles row=tid&15, 16 contiguous j
        int r = tid & 15, jb = (tid >> 4) * 16;
        const float* src = &g_x0[(row0 + r) * NH + jb];
#pragma unroll
        for (int i = 0; i < 16; i++) {
            int j = jb + i;
            int colp = NH + (j & ~7) + kpos(j & 7);
            float v = src[i];
            unsigned hv = tf32r(v);
            smemu[AH + r * SROW + colp] = hv;
            smemu[AL + r * SROW + colp] = tf32r(v - __uint_as_float(hv));
        }
    }
    float cst[16];
#pragma unroll
    for (int i = 0; i < 16; i++) cst[i] = 0.0f;
    __syncthreads();

    const float4* __restrict__ Bw = g_bp + (size_t)w * (KSUB * 16 * 32) + lane;
    const int myrow = g0 + 8 * (tig & 1);

    for (int t = 0; t < NT; t++) {
        // finalize out(t-1)
        if (t > 0 && tid < 16) {
            float s = b_out0;
#pragma unroll
            for (int q = 0; q < 8; q++) s += outpf[tid * 8 + q];
            out[(size_t)(t - 1) * NGRID + row0 + tid] = s;
        }

        float C0[16], C1[16], C2[16], C3[16];
#pragma unroll
        for (int i = 0; i < 16; i++) { C0[i] = 0.f; C1[i] = 0.f; C2[i] = 0.f; C3[i] = 0.f; }

#pragma unroll 1
        for (int ks = 0; ks < KSUB; ks++) {
            float4 b[16];
#pragma unroll
            for (int ns = 0; ns < 16; ns++) b[ns] = Bw[ks * 512 + ns * 32];
            int cb = ks * 8 + 2 * tig;
            uint2 h01 = *(const uint2*)&smemu[AH + g0 * SROW + cb];
            uint2 h23 = *(const uint2*)&smemu[AH + (g0 + 8) * SROW + cb];
            uint2 l01 = *(const uint2*)&smemu[AL + g0 * SROW + cb];
            uint2 l23 = *(const uint2*)&smemu[AL + (g0 + 8) * SROW + cb];
#pragma unroll
            for (int ns = 0; ns < 16; ns++) {
                unsigned bh0 = __float_as_uint(b[ns].x), bh1 = __float_as_uint(b[ns].y);
                unsigned bl0 = __float_as_uint(b[ns].z), bl1 = __float_as_uint(b[ns].w);
                mma8(C0[ns], C1[ns], C2[ns], C3[ns], h01.x, h23.x, h01.y, h23.y, bh0, bh1);
                mma8(C0[ns], C1[ns], C2[ns], C3[ns], h01.x, h23.x, h01.y, h23.y, bl0, bl1);
                mma8(C0[ns], C1[ns], C2[ns], C3[ns], l01.x, l23.x, l01.y, l23.y, bh0, bh1);
            }
        }
        __syncthreads();   // all act reads done

        // prefetch x0(t+1) for this thread's slice
        float4 xv[4];
        int xr = tid & 15, xjb = (tid >> 4) * 16;
        if (t + 1 < NT) {
            const float4* src =
                (const float4*)&g_x0[((size_t)(t + 1) * NGRID + row0 + xr) * NH + xjb];
#pragma unroll
            for (int q = 0; q < 4; q++) xv[q] = src[q];
        }

        // gates -> h,c ; write h(t) into act ; accumulate out partial
        float partial = 0.0f;
#pragma unroll
        for (int ns = 0; ns < 16; ns++) {
            float s0 = (tig & 1) ? C0[ns] : C2[ns];
            float s1 = (tig & 1) ? C1[ns] : C3[ns];
            float r0 = __shfl_xor_sync(0xffffffffu, s0, 1);
            float r1 = __shfl_xor_sync(0xffffffffu, s1, 1);
            float gi, gf, gg, go;
            if ((tig & 1) == 0) { gi = C0[ns]; gf = C1[ns]; gg = r0; go = r1; }
            else                { gi = r0;     gf = r1;     gg = C2[ns]; go = C3[ns]; }
            int ug = w * 32 + 2 * ns + (tig >> 1);
            float4 bs = *(const float4*)&biasf[ug * 4];
            float iv = sigf(gi + bs.x);
            float fv = sigf(gf + bs.y);
            float gv = tanhf(gg + bs.z);
            float ov = sigf(go + bs.w);
            float c = fmaf(fv, cst[ns], iv * gv);
            cst[ns] = c;
            float h = ov * tanhf(c);
            partial = fmaf(h, woutf[ug], partial);
            int colp = (ug & ~7) + kpos(ug & 7);
            unsigned hh = tf32r(h);
            smemu[AH + myrow * SROW + colp] = hh;
            smemu[AL + myrow * SROW + colp] = tf32r(h - __uint_as_float(hh));
        }
        partial += __shfl_xor_sync(0xffffffffu, partial, 2);
        if (tig < 2) outpf[myrow * 8 + w] = partial;

        // store x0(t+1)
        if (t + 1 < NT) {
            const float* xf = (const float*)xv;
#pragma unroll
            for (int i = 0; i < 16; i++) {
                int j = xjb + i;
                int colp = NH + (j & ~7) + kpos(j & 7);
                float v = xf[i];
                unsigned hv = tf32r(v);
                smemu[AH + xr * SROW + colp] = hv;
                smemu[AL + xr * SROW + colp] = tf32r(v - __uint_as_float(hv));
            }
        }
        __syncthreads();   // act(t+1) ready
    }
    // final timestep output
    if (tid < 16) {
        float s = b_out0;
#pragma unroll
        for (int q = 0; q < 8; q++) s += outpf[tid * 8 + q];
        out[(size_t)(NT - 1) * NGRID + row0 + tid] = s;
    }
}

// ---------------- launch ----------------
extern "C" void kernel_launch(void* const* d_in, const int* in_sizes, int n_in,
                              void* d_out, int out_size) {
    const float* x     = (const float*)d_in[0];
    const float* w_in  = (const float*)d_in[1];
    const float* b_in  = (const float*)d_in[2];
    const float* w_ih  = (const float*)d_in[3];
    const float* w_hh  = (const float*)d_in[4];
    const float* b_ih  = (const float*)d_in[5];
    const float* b_hh  = (const float*)d_in[6];
    const float* w_out = (const float*)d_in[7];
    const float* b_out = (const float*)d_in[8];
    float* out = (float*)d_out;

    const int smem_scan = (2 * 16 * SROW + 1024 + 256 + 128) * (int)sizeof(unsigned);
    cudaFuncSetAttribute(lstm_scan, cudaFuncAttributeMaxDynamicSharedMemorySize,
                         smem_scan);

    pack_weights<<<1024, 256>>>(w_ih, w_hh);
    in_proj<<<NROWS / 16, 256>>>(x, w_in, b_in);
    lstm_scan<<<NGRID / 16, 256, smem_scan>>>(b_ih, b_hh, w_out, b_out, out);
}

// round 7
// speedup vs baseline: 2.6560x; 1.7682x over previous
#include <cuda_runtime.h>
#include <cuda_bf16.h>
#include <math.h>

#define NT     365
#define NGRID  2048
#define NX     16
#define NH     256
#define G4     1024              // 4*NH
#define K2     512               // combined k = NH (h) + NH (x0)
#define NROWS  (NT * NGRID)      // 747520
#define KS16   32                // K2/16 k-tiles
#define ROW_BF 528               // act row stride in bf16 units (264 words; 264%32==8)
#define ROW_B  1056              // act row stride in bytes

// ---------------- scratch (static __device__) -- keep total < 2GB ----------------
__device__ float  g_x0[(size_t)NROWS * NH];            // ~765 MB
__device__ float4 g_bp[8 * KS16 * 16 * 32];            // packed B fragments, 2 MB

// permuted bf16 position within a row for global k (16-groups, pairs interleaved
// so that k-pairs (2tig) and (2tig+8) are adjacent -> one LDS.64 per A frag pair)
__device__ __forceinline__ int bpos(int k) {
    int grp = k & ~15, q = k & 15, pj = q >> 1;
    int pp = (pj < 4) ? 2 * pj : 2 * pj - 7;
    return grp + 2 * pp + (q & 1);
}

__device__ __forceinline__ float sigf(float x) { return 1.0f / (1.0f + __expf(-x)); }

__device__ __forceinline__ unsigned bfpack2(float lo, float hi) {
    unsigned short a = __bfloat16_as_ushort(__float2bfloat16_rn(lo));
    unsigned short b = __bfloat16_as_ushort(__float2bfloat16_rn(hi));
    return (unsigned)a | ((unsigned)b << 16);
}

// m16n8k16 bf16 mma, f32 accum. Operand order: a1 = row+8 / same k (R4 lesson).
__device__ __forceinline__ void mma16(float& c0, float& c1, float& c2, float& c3,
                                      unsigned a0, unsigned a1, unsigned a2, unsigned a3,
                                      unsigned b0, unsigned b1) {
    asm("mma.sync.aligned.m16n8k16.row.col.f32.bf16.bf16.f32 "
        "{%0,%1,%2,%3},{%4,%5,%6,%7},{%8,%9},{%0,%1,%2,%3};"
        : "+f"(c0), "+f"(c1), "+f"(c2), "+f"(c3)
        : "r"(a0), "r"(a1), "r"(a2), "r"(a3), "r"(b0), "r"(b1));
}

// ---------------- kernel 0: pack B fragments (hi/lo bf16) ----------------
// B[k][col]: col=(u<<2)|gate; k<256 -> w_hh[gate*NH+u][k], else w_ih[...][k-256]
// frag (w,ks,ns,lane): b0 = k-pair (16ks+2tig, +1), b1 = (16ks+2tig+8, +9), col=128w+8ns+g0
// index bits: lane[0:5) ns[5:9) ks[9:14) w[14:17)   (R6 bug: w was idx>>13)
__global__ void pack_weights(const float* __restrict__ w_ih,
                             const float* __restrict__ w_hh) {
    int idx = blockIdx.x * 256 + threadIdx.x;        // 0..131071
    int lane = idx & 31, ns = (idx >> 5) & 15, ks = (idx >> 9) & 31, w = idx >> 14;
    int g0 = lane >> 2, tig = lane & 3;
    int col = w * 128 + ns * 8 + g0;
    int u = col >> 2, gate = col & 3;
    int jrow = gate * NH + u;
    float v[4]; float hi[4]; float lo[4];
#pragma unroll
    for (int e = 0; e < 4; e++) {
        int k = ks * 16 + 2 * tig + (e & 1) + (e >> 1) * 8;
        v[e] = (k < NH) ? w_hh[jrow * NH + k] : w_ih[jrow * NH + k - NH];
        hi[e] = __bfloat162float(__float2bfloat16_rn(v[e]));
        lo[e] = v[e] - hi[e];
    }
    float4 r;
    r.x = __uint_as_float(bfpack2(hi[0], hi[1]));
    r.y = __uint_as_float(bfpack2(hi[2], hi[3]));
    r.z = __uint_as_float(bfpack2(lo[0], lo[1]));
    r.w = __uint_as_float(bfpack2(lo[2], lo[3]));
    g_bp[idx] = r;
}

// ---------------- kernel 1: x0 = relu(x @ w_in^T + b_in) ----------------
__global__ __launch_bounds__(256) void in_proj(const float* __restrict__ x,
                                               const float* __restrict__ w_in,
                                               const float* __restrict__ b_in) {
    __shared__ float ws[NX][NH];
    __shared__ float xs[16][NX];
    int tid = threadIdx.x;
    for (int i = tid; i < NH * NX; i += 256) {
        int u = i >> 4, k = i & 15;
        ws[k][u] = w_in[i];
    }
    size_t row0 = (size_t)blockIdx.x * 16;
    {
        int r = tid >> 4, k = tid & 15;
        xs[r][k] = x[(row0 + r) * NX + k];
    }
    __syncthreads();
    int u = tid;
    float b = b_in[u];
#pragma unroll 4
    for (int r = 0; r < 16; r++) {
        float s = b;
#pragma unroll
        for (int k = 0; k < NX; k++) s = fmaf(xs[r][k], ws[k][u], s);
        g_x0[(row0 + r) * NH + u] = fmaxf(s, 0.0f);
    }
}

// ---------------- kernel 2: persistent fused LSTM scan, bf16x3 mma ----------------
// 128 CTAs x 256 threads (8 warps). CTA owns 16 rows. Warp w owns gate-interleaved
// N-slice [128w,128w+128). A = [16 rows][512 k] act (h|x0), bf16 hi+lo planes in
// SMEM with pair-granular k permutation. 3 passes: hi*hi + hi*lo + lo*hi.
__global__ __launch_bounds__(256, 1) void lstm_scan(const float* __restrict__ b_ih,
                                                    const float* __restrict__ b_hh,
                                                    const float* __restrict__ w_out,
                                                    const float* __restrict__ b_out,
                                                    float* __restrict__ out) {
    extern __shared__ unsigned smemu[];
    // bytes: actH [16*ROW_B], actL [16*ROW_B], then words: bias[1024], wout[256], outp[128]
    const int AHW = 0;                         // act hi, word offset
    const int ALW = 16 * ROW_B / 4;            // act lo
    const int BI = 2 * 16 * ROW_B / 4, WO = BI + 1024, OP = WO + 256;
    float* biasf = (float*)&smemu[BI];
    float* woutf = (float*)&smemu[WO];
    float* outpf = (float*)&smemu[OP];
    unsigned short* aH = (unsigned short*)&smemu[AHW];
    unsigned short* aL = (unsigned short*)&smemu[ALW];
    const char* cH = (const char*)&smemu[AHW];
    const char* cL = (const char*)&smemu[ALW];

    const int tid = threadIdx.x;
    const int w = tid >> 5, lane = tid & 31;
    const int g0 = lane >> 2, tig = lane & 3;
    const size_t row0 = (size_t)blockIdx.x * 16;
    const float b_out0 = b_out[0];

    for (int j = tid; j < G4; j += 256)
        biasf[j] = b_ih[(j & 3) * NH + (j >> 2)] + b_hh[(j & 3) * NH + (j >> 2)];
    woutf[tid] = w_out[tid];
    for (int i = tid; i < 2 * 16 * (ROW_B / 4); i += 256) smemu[i] = 0u;
    __syncthreads();
    {   // x0(t=0): thread handles row=tid&15, 16 consecutive x-units
        int r = tid & 15, jb = (tid >> 4) * 16;
        const float* src = &g_x0[(row0 + r) * NH + jb];
#pragma unroll
        for (int i = 0; i < 16; i++) {
            int colp = bpos(NH + jb + i);
            float v = src[i];
            float hv = __bfloat162float(__float2bfloat16_rn(v));
            aH[r * ROW_BF + colp] = __bfloat16_as_ushort(__float2bfloat16_rn(v));
            aL[r * ROW_BF + colp] = __bfloat16_as_ushort(__float2bfloat16_rn(v - hv));
        }
    }
    float cst[16];
#pragma unroll
    for (int i = 0; i < 16; i++) cst[i] = 0.0f;
    __syncthreads();

    const float4* __restrict__ Bw = g_bp + (size_t)w * (KS16 * 16 * 32) + lane;
    const int myrow = g0 + 8 * (tig & 1);
    const int aoff = tig * 8;   // byte offset within k-tile for this lane's A frags

    for (int t = 0; t < NT; t++) {
        // finalize out(t-1)
        if (t > 0 && tid < 16) {
            float s = b_out0;
#pragma unroll
            for (int q = 0; q < 8; q++) s += outpf[tid * 8 + q];
            out[(size_t)(t - 1) * NGRID + row0 + tid] = s;
        }

        float C0[16], C1[16], C2[16], C3[16];
#pragma unroll
        for (int i = 0; i < 16; i++) { C0[i] = 0.f; C1[i] = 0.f; C2[i] = 0.f; C3[i] = 0.f; }

        float4 bcur[16];
#pragma unroll
        for (int ns = 0; ns < 16; ns++) bcur[ns] = Bw[ns * 32];

#pragma unroll 1
        for (int ks = 0; ks < KS16; ks++) {
            float4 bnxt[16];
            int ks2 = (ks + 1) & (KS16 - 1);   // wrap: last-iter loads are dead but in-bounds
#pragma unroll
            for (int ns = 0; ns < 16; ns++) bnxt[ns] = Bw[ks2 * 512 + ns * 32];

            uint2 h_r0 = *(const uint2*)(cH + g0 * ROW_B + ks * 32 + aoff);
            uint2 h_r8 = *(const uint2*)(cH + (g0 + 8) * ROW_B + ks * 32 + aoff);
            uint2 l_r0 = *(const uint2*)(cL + g0 * ROW_B + ks * 32 + aoff);
            uint2 l_r8 = *(const uint2*)(cL + (g0 + 8) * ROW_B + ks * 32 + aoff);
#pragma unroll
            for (int ns = 0; ns < 16; ns++) {
                unsigned bh0 = __float_as_uint(bcur[ns].x), bh1 = __float_as_uint(bcur[ns].y);
                unsigned bl0 = __float_as_uint(bcur[ns].z), bl1 = __float_as_uint(bcur[ns].w);
                mma16(C0[ns], C1[ns], C2[ns], C3[ns], h_r0.x, h_r8.x, h_r0.y, h_r8.y, bh0, bh1);
                mma16(C0[ns], C1[ns], C2[ns], C3[ns], h_r0.x, h_r8.x, h_r0.y, h_r8.y, bl0, bl1);
                mma16(C0[ns], C1[ns], C2[ns], C3[ns], l_r0.x, l_r8.x, l_r0.y, l_r8.y, bh0, bh1);
            }
#pragma unroll
            for (int ns = 0; ns < 16; ns++) bcur[ns] = bnxt[ns];
        }
        __syncthreads();   // all act reads done

        // prefetch x0(t+1) for this thread's slice
        float4 xv[4];
        int xr = tid & 15, xjb = (tid >> 4) * 16;
        if (t + 1 < NT) {
            const float4* src =
                (const float4*)&g_x0[((size_t)(t + 1) * NGRID + row0 + xr) * NH + xjb];
#pragma unroll
            for (int q = 0; q < 4; q++) xv[q] = src[q];
        }

        // gates -> h,c ; write h(t) bf16 hi/lo into act ; accumulate out partial
        float partial = 0.0f;
#pragma unroll
        for (int ns = 0; ns < 16; ns++) {
            float s0 = (tig & 1) ? C0[ns] : C2[ns];
            float s1 = (tig & 1) ? C1[ns] : C3[ns];
            float r0 = __shfl_xor_sync(0xffffffffu, s0, 1);
            float r1 = __shfl_xor_sync(0xffffffffu, s1, 1);
            float gi, gf, gg, go;
            if ((tig & 1) == 0) { gi = C0[ns]; gf = C1[ns]; gg = r0; go = r1; }
            else                { gi = r0;     gf = r1;     gg = C2[ns]; go = C3[ns]; }
            int ug = w * 32 + 2 * ns + (tig >> 1);
            float4 bs = *(const float4*)&biasf[ug * 4];
            float iv = sigf(gi + bs.x);
            float fv = sigf(gf + bs.y);
            float gv = tanhf(gg + bs.z);
            float ov = sigf(go + bs.w);
            float c = fmaf(fv, cst[ns], iv * gv);
            cst[ns] = c;
            float h = ov * tanhf(c);
            partial = fmaf(h, woutf[ug], partial);
            int colp = bpos(ug);
            float hv = __bfloat162float(__float2bfloat16_rn(h));
            aH[myrow * ROW_BF + colp] = __bfloat16_as_ushort(__float2bfloat16_rn(h));
            aL[myrow * ROW_BF + colp] = __bfloat16_as_ushort(__float2bfloat16_rn(h - hv));
        }
        partial += __shfl_xor_sync(0xffffffffu, partial, 2);
        if (tig < 2) outpf[myrow * 8 + w] = partial;

        // store x0(t+1) bf16 hi/lo
        if (t + 1 < NT) {
            const float* xf = (const float*)xv;
#pragma unroll
            for (int i = 0; i < 16; i++) {
                int colp = bpos(NH + xjb + i);
                float v = xf[i];
                float hv = __bfloat162float(__float2bfloat16_rn(v));
                aH[xr * ROW_BF + colp] = __bfloat16_as_ushort(__float2bfloat16_rn(v));
                aL[xr * ROW_BF + colp] = __bfloat16_as_ushort(__float2bfloat16_rn(v - hv));
            }
        }
        __syncthreads();   // act(t+1) ready
    }
    // final timestep output
    if (tid < 16) {
        float s = b_out0;
#pragma unroll
        for (int q = 0; q < 8; q++) s += outpf[tid * 8 + q];
        out[(size_t)(NT - 1) * NGRID + row0 + tid] = s;
    }
}

// ---------------- launch ----------------
extern "C" void kernel_launch(void* const* d_in, const int* in_sizes, int n_in,
                              void* d_out, int out_size) {
    const float* x     = (const float*)d_in[0];
    const float* w_in  = (const float*)d_in[1];
    const float* b_in  = (const float*)d_in[2];
    const float* w_ih  = (const float*)d_in[3];
    const float* w_hh  = (const float*)d_in[4];
    const float* b_ih  = (const float*)d_in[5];
    const float* b_hh  = (const float*)d_in[6];
    const float* w_out = (const float*)d_in[7];
    const float* b_out = (const float*)d_in[8];
    float* out = (float*)d_out;

    const int smem_scan = 2 * 16 * ROW_B + (1024 + 256 + 128) * (int)sizeof(float);
    cudaFuncSetAttribute(lstm_scan, cudaFuncAttributeMaxDynamicSharedMemorySize,
                         smem_scan);

    pack_weights<<<512, 256>>>(w_ih, w_hh);
    in_proj<<<NROWS / 16, 256>>>(x, w_in, b_in);
    lstm_scan<<<NGRID / 16, 256, smem_scan>>>(b_ih, b_hh, w_out, b_out, out);
}